// round 11
// baseline (speedup 1.0000x reference)
#include <cuda_runtime.h>
#include <cuda_fp16.h>
#include <cstdint>
#include <math.h>

// ---------------- problem constants -----------------------------------------
#define E_      8
#define D_      1024
#define H_      1024
#define H2_     2048
#define NTOK_   2048
#define NPAIR_  4096

// ---------------- scratch (__device__ globals; no allocations) --------------
__device__ int   g_cnt[E_];
__device__ int   g_perm[E_ * NPAIR_];
__device__ __half g_xh[(size_t)NTOK_ * D_];                  // x fp16
__device__ __half g_ah[(size_t)NPAIR_ * H_];                 // act fp16
__device__ __half g_w1h[(size_t)E_ * H2_ * D_];              // W1^T interleaved [e][n'][k]
__device__ __half g_w2h[(size_t)E_ * D_ * H_];               // W2^T [e][n][k]

// ---------------- shared transpose tile helper (fp32 [k][n] -> fp16 [n][k]) --
// Tile: 64 k x 32 n. Writes 8B (4 fp16 along k) per store, coalesced per n-row.
// inter=true applies the W1 h/g interleave: n<1024 -> row 2n; else 2(n-1024)+1.
__device__ __forceinline__ void transpose_tile(const float* __restrict__ src,
        __half* __restrict__ dst, int N, int e, int kt, int nt, bool inter,
        char* smptr)
{
    float (*t)[33] = (float (*)[33])smptr;              // 64 x 33 fp32 = 8448 B
    const int K = 1024;
    const float* s = src + (size_t)e * K * N;
    const size_t dbase = (size_t)e * K * N;
    const int k0 = kt * 64, n0 = nt * 32;
    const int tid = threadIdx.x;
    const int r = tid >> 5, c = tid & 31;
    #pragma unroll
    for (int i = 0; i < 8; i++)
        t[r + 8 * i][c] = s[(size_t)(k0 + r + 8 * i) * N + n0 + c];
    __syncthreads();
    const int kl = (tid & 15) * 4;
    #pragma unroll
    for (int it = 0; it < 2; it++) {
        int nl = (tid >> 4) + 16 * it;
        int n  = n0 + nl;
        int np = inter ? ((n < 1024) ? 2 * n : 2 * (n - 1024) + 1) : n;
        __half2 p0 = __floats2half2_rn(t[kl][nl],     t[kl + 1][nl]);
        __half2 p1 = __floats2half2_rn(t[kl + 2][nl], t[kl + 3][nl]);
        uint2 pk;
        pk.x = *(uint32_t*)&p0;
        pk.y = *(uint32_t*)&p1;
        *(uint2*)(dst + dbase + (size_t)np * K + k0 + kl) = pk;
    }
}

// ---------------- K1: fused prep = zero | route | cvt_x | W1T | W2T ----------
// [0,2048) zero; [2048] route; [2049,4097) cvt_x;
// [4097,12289) W1 transpose (8e x 16kt x 64nt);
// [12289,16385) W2 transpose (8e x 16kt x 32nt).
#define PREP_BLOCKS (2048 + 1 + 2048 + 8192 + 4096)

__global__ void __launch_bounds__(256) prep_kernel(const float4* __restrict__ x,
                                                   const int* __restrict__ idx,
                                                   float4* __restrict__ out,
                                                   const float* __restrict__ W1,
                                                   const float* __restrict__ W2) {
    __shared__ __align__(16) char tsm[64 * 33 * 4];
    __shared__ int cnt8[E_];
    const int bx = blockIdx.x, tid = threadIdx.x;

    if (bx < 2048) {                                     // zero output
        out[bx * 256 + tid] = make_float4(0.f, 0.f, 0.f, 0.f);
    } else if (bx == 2048) {                             // route (single block)
        if (tid < E_) cnt8[tid] = 0;
        __syncthreads();
        for (int j = 0; j < 16; j++) {
            int i = tid + 256 * j;                       // 4096 pairs
            int e = idx[i];
            int pos = atomicAdd(&cnt8[e], 1);
            g_perm[e * NPAIR_ + pos] = i;
        }
        __syncthreads();
        if (tid < E_) g_cnt[tid] = cnt8[tid];
    } else if (bx < 4097) {                              // cvt x -> fp16
        int i = (bx - 2049) * 256 + tid;                 // 512K float4
        float4 v = x[i];
        ((__half2*)g_xh)[2 * i]     = __floats2half2_rn(v.x, v.y);
        ((__half2*)g_xh)[2 * i + 1] = __floats2half2_rn(v.z, v.w);
    } else if (bx < 12289) {                             // W1 transpose+interleave
        int b   = bx - 4097;
        int e   = b >> 10;                               // 1024 tiles/expert
        int rem = b & 1023;
        int kt  = rem & 15;
        int nt  = rem >> 4;
        transpose_tile(W1, g_w1h, H2_, e, kt, nt, true, tsm);
    } else {                                             // W2 transpose
        int b   = bx - 12289;
        int e   = b >> 9;                                // 512 tiles/expert
        int rem = b & 511;
        int kt  = rem & 15;
        int nt  = rem >> 4;
        transpose_tile(W2, g_w2h, H_, e, kt, nt, false, tsm);
    }
}

// ---------------- warp-level helpers ------------------------------------------
// fp16-accumulate mma: d,c are 2 regs (4 halves). Promoted to fp32 per k-step.
__device__ __forceinline__ void mma16816_f16(uint32_t* c, const uint32_t* a,
                                             const uint32_t* b) {
    asm volatile(
        "mma.sync.aligned.m16n8k16.row.col.f16.f16.f16.f16 "
        "{%0,%1}, {%2,%3,%4,%5}, {%6,%7}, {%0,%1};"
        : "+r"(c[0]), "+r"(c[1])
        : "r"(a[0]), "r"(a[1]), "r"(a[2]), "r"(a[3]), "r"(b[0]), "r"(b[1]));
}
__device__ __forceinline__ void ldsm4(uint32_t* d, uint32_t a) {
    asm volatile("ldmatrix.sync.aligned.m8n8.x4.shared.b16 {%0,%1,%2,%3}, [%4];"
                 : "=r"(d[0]), "=r"(d[1]), "=r"(d[2]), "=r"(d[3]) : "r"(a));
}
__device__ __forceinline__ void cpasync16(uint32_t dst, const void* src, int sz) {
    asm volatile("cp.async.cg.shared.global [%0], [%1], 16, %2;"
                 :: "r"(dst), "l"(src), "r"(sz) : "memory");
}
__device__ __forceinline__ uint32_t smem_u32(const void* p) {
    uint32_t a;
    asm("{ .reg .u64 t; cvta.to.shared.u64 t, %1; cvt.u32.u64 %0, t; }" : "=r"(a) : "l"(p));
    return a;
}

// ---------------- GEMM: 128x128 CTA, 8 warps (2x4), warp 64x32, KC=64 --------
// SMEM: rowoff[128] @0; 3 stages @1024 + s*32768: A(16K) B(16K); 128B rows,
// 16B-chunk swizzle (chunk ^ (row&7)) -> conflict-free cp.async + ldmatrix.
// 2 CTAs/SM. RATE EXPERIMENT: fp16-accumulate HMMA (one k16 per mma, rounded
// once at sigma~0.125 of output scale) promoted to fp32 master acc each
// k-step. If the legacy tensor path runs f16-acc at 2x f32-acc (consumer
// behavior), GEMM drops ~40%.
#define KC       64
#define STAGE_B  32768
#define NSTAGE   3
#define SMEM_DYN (1024 + NSTAGE * STAGE_B)
#define MTMAX    (NPAIR_ / 128)

__global__ void __launch_bounds__(256, 2) moe_gemm_kernel(
    const float* __restrict__ pgate, float* __restrict__ out, int mode, int Ntot)
{
    const int e     = blockIdx.z;
    const int cnt   = g_cnt[e];
    const int mTile = blockIdx.y;
    if (mTile * 128 >= cnt) return;
    const int nTile = blockIdx.x;

    extern __shared__ char smem[];
    int* rowoff = (int*)smem;
    const uint32_t sbase = smem_u32(smem);

    const int tid  = threadIdx.x;
    const int wid  = tid >> 5;
    const int lane = tid & 31;
    const int wm   = wid & 1;          // 0..1
    const int wn   = wid >> 1;         // 0..3

    const __half* A  = (mode == 1) ? g_xh  : g_ah;
    const __half* Bh = (mode == 1) ? g_w1h : g_w2h;
    Bh += ((size_t)e * Ntot + (size_t)nTile * 128) * 1024;

    if (tid < 128) {
        int rg = mTile * 128 + tid;
        int off = -1;
        if (rg < cnt) {
            int pair = g_perm[e * NPAIR_ + rg];
            off = (mode == 1) ? ((pair >> 1) << 10) : (pair << 10);
        }
        rowoff[tid] = off;
    }
    __syncthreads();

    // ---- cp.async stage loader: thread t -> row r=t/2, 4 16B chunks/array ---
    const int lr  = tid >> 1;
    const int lcb = (tid & 1) * 4;
    const int lrx = lr & 7;
    auto issue_stage = [&](int c) {
        const int k0 = c * KC;
        const uint32_t stb = sbase + 1024 + (c % NSTAGE) * STAGE_B;
        const uint32_t dA = stb + lr * 128;
        int ao = rowoff[lr];
        int sz = (ao >= 0) ? 16 : 0;
        const __half* aph = A  + (ao >= 0 ? ao : 0) + k0 + lcb * 8;
        const __half* bph = Bh + (size_t)lr * 1024 + k0 + lcb * 8;
        #pragma unroll
        for (int i = 0; i < 4; i++) {
            uint32_t sw = (uint32_t)(((lcb + i) ^ lrx) << 4);
            cpasync16(dA + sw,         aph + i * 8, sz);
            cpasync16(dA + 16384 + sw, bph + i * 8, 16);
        }
        asm volatile("cp.async.commit_group;" ::: "memory");
    };

    // ---- per-lane ldmatrix address bases ------------------------------------
    const int g  = lane >> 3;
    const int r8 = lane & 7;
    uint32_t aRowOff[4], bRowOff[2];
    #pragma unroll
    for (int mf = 0; mf < 4; mf++)
        aRowOff[mf] = (uint32_t)((wm * 64 + mf * 16 + (g & 1) * 8 + r8) * 128);
    #pragma unroll
    for (int j = 0; j < 2; j++)
        bRowOff[j] = (uint32_t)((wn * 32 + j * 16 + (g >> 1) * 8 + r8) * 128) + 16384;
    const int acadd = g >> 1;
    const int bcadd = g & 1;

    float acc[4][4][4];
    #pragma unroll
    for (int i = 0; i < 4; i++)
        #pragma unroll
        for (int j = 0; j < 4; j++)
            #pragma unroll
            for (int q = 0; q < 4; q++) acc[i][j][q] = 0.f;

    issue_stage(0);
    issue_stage(1);

    const int NCH = 1024 / KC;   // 16
    for (int c = 0; c < NCH; c++) {
        if (c < NCH - 1) asm volatile("cp.async.wait_group 1;" ::: "memory");
        else             asm volatile("cp.async.wait_group 0;" ::: "memory");
        __syncthreads();
        if (c + 2 < NCH) issue_stage(c + 2);

        const uint32_t stb = sbase + 1024 + (c % NSTAGE) * STAGE_B;
        #pragma unroll
        for (int s = 0; s < 4; s++) {
            uint32_t ah[4][4], bh[2][4];
            const uint32_t asw = (uint32_t)((((s * 2 + acadd) ^ r8) << 4));
            const uint32_t bsw = (uint32_t)((((s * 2 + bcadd) ^ r8) << 4));
            #pragma unroll
            for (int mf = 0; mf < 4; mf++)
                ldsm4(ah[mf], stb + aRowOff[mf] + asw);
            #pragma unroll
            for (int j = 0; j < 2; j++)
                ldsm4(bh[j], stb + bRowOff[j] + bsw);
            #pragma unroll
            for (int mf = 0; mf < 4; mf++)
                #pragma unroll
                for (int nf = 0; nf < 4; nf++) {
                    const int jj = nf >> 1, hh = nf & 1;
                    uint32_t bhp[2] = { bh[jj][2 * hh], bh[jj][2 * hh + 1] };
                    uint32_t c2[2] = { 0u, 0u };
                    mma16816_f16(c2, ah[mf], bhp);
                    float2 lo = __half22float2(*(__half2*)&c2[0]);
                    float2 hi = __half22float2(*(__half2*)&c2[1]);
                    acc[mf][nf][0] += lo.x;
                    acc[mf][nf][1] += lo.y;
                    acc[mf][nf][2] += hi.x;
                    acc[mf][nf][3] += hi.y;
                }
        }
    }

    // ---- epilogue ----
    const int gr  = lane >> 2;
    const int lc2 = (lane & 3) * 2;
    #pragma unroll
    for (int mf = 0; mf < 4; mf++) {
        #pragma unroll
        for (int half = 0; half < 2; half++) {
            int r   = wm * 64 + mf * 16 + gr + half * 8;
            int rg2 = mTile * 128 + r;
            if (rg2 < cnt) {
                int pair = g_perm[e * NPAIR_ + rg2];
                if (mode == 1) {
                    // interleaved: acc col pair (lc2, lc2+1) = (h, g) for
                    // logical act col nTile*64 + (wn*32 + nf*8 + lc2)/2
                    __half* dst = g_ah + (size_t)pair * H_ + (size_t)nTile * 64;
                    #pragma unroll
                    for (int nf = 0; nf < 4; nf++) {
                        float h  = acc[mf][nf][half * 2];
                        float gg = acc[mf][nf][half * 2 + 1];
                        float a  = h * gg / (1.f + __expf(-gg));
                        int n = (wn * 32 + nf * 8 + lc2) >> 1;
                        dst[n] = __float2half_rn(a);
                    }
                } else {
                    float pc = pgate[pair];
                    float* dst = out + (size_t)(pair >> 1) * D_ + (size_t)nTile * 128;
                    #pragma unroll
                    for (int nf = 0; nf < 4; nf++) {
                        int n = wn * 32 + nf * 8 + lc2;
                        atomicAdd(dst + n,     acc[mf][nf][half * 2]     * pc);
                        atomicAdd(dst + n + 1, acc[mf][nf][half * 2 + 1] * pc);
                    }
                }
            }
        }
    }
}

// ---------------- launch ------------------------------------------------------
extern "C" void kernel_launch(void* const* d_in, const int* in_sizes, int n_in,
                              void* d_out, int out_size) {
    const float* x   = (const float*)d_in[0];   // [2,1024,1024] f32
    const float* p   = (const float*)d_in[1];   // [2048,2]      f32
    const int*   idx = (const int*)  d_in[2];   // [2048,2]      int32
    const float* W1  = (const float*)d_in[3];   // [8,1024,2048] f32
    const float* W2  = (const float*)d_in[4];   // [8,1024,1024] f32
    float*       out = (float*)d_out;           // [2,1024,1024] f32
    (void)in_sizes; (void)n_in; (void)out_size;

    cudaFuncSetAttribute(moe_gemm_kernel,
                         cudaFuncAttributeMaxDynamicSharedMemorySize, SMEM_DYN);

    // K1: zero + route + cvt_x + W1T + W2T (fused)
    prep_kernel<<<PREP_BLOCKS, 256>>>((const float4*)x, idx, (float4*)out, W1, W2);
    // K2: GEMM1 (+fused SiLU epilogue)
    moe_gemm_kernel<<<dim3(H2_/128, MTMAX, E_), 256, SMEM_DYN>>>(p, out, 1, H2_);
    // K3: GEMM2 (+gated atomic combine)
    moe_gemm_kernel<<<dim3(D_/128, MTMAX, E_), 256, SMEM_DYN>>>(p, out, 2, D_);
}

// round 12
// speedup vs baseline: 1.3016x; 1.3016x over previous
#include <cuda_runtime.h>
#include <cuda_fp16.h>
#include <cstdint>
#include <math.h>

// ---------------- problem constants -----------------------------------------
#define E_      8
#define D_      1024
#define H_      1024
#define H2_     2048
#define NTOK_   2048
#define NPAIR_  4096

// ---------------- scratch (__device__ globals; no allocations) --------------
__device__ int   g_cnt[E_];
__device__ int   g_perm[E_ * NPAIR_];
__device__ __half g_xh[(size_t)NTOK_ * D_];                  // x fp16
__device__ __half g_ah[(size_t)NPAIR_ * H_];                 // act fp16
__device__ __half g_w1h[(size_t)E_ * H2_ * D_];              // W1^T interleaved [e][n'][k]
__device__ __half g_w2h[(size_t)E_ * D_ * H_];               // W2^T [e][n][k]

// ---------------- shared transpose tile helper (fp32 [k][n] -> fp16 [n][k]) --
__device__ __forceinline__ void transpose_tile(const float* __restrict__ src,
        __half* __restrict__ dst, int N, int e, int kt, int nt, bool inter,
        char* smptr)
{
    float (*t)[33] = (float (*)[33])smptr;              // 64 x 33 fp32
    const int K = 1024;
    const float* s = src + (size_t)e * K * N;
    const size_t dbase = (size_t)e * K * N;
    const int k0 = kt * 64, n0 = nt * 32;
    const int tid = threadIdx.x;
    const int r = tid >> 5, c = tid & 31;
    #pragma unroll
    for (int i = 0; i < 8; i++)
        t[r + 8 * i][c] = s[(size_t)(k0 + r + 8 * i) * N + n0 + c];
    __syncthreads();
    const int kl = (tid & 15) * 4;
    #pragma unroll
    for (int it = 0; it < 2; it++) {
        int nl = (tid >> 4) + 16 * it;
        int n  = n0 + nl;
        int np = inter ? ((n < 1024) ? 2 * n : 2 * (n - 1024) + 1) : n;
        __half2 p0 = __floats2half2_rn(t[kl][nl],     t[kl + 1][nl]);
        __half2 p1 = __floats2half2_rn(t[kl + 2][nl], t[kl + 3][nl]);
        uint2 pk;
        pk.x = *(uint32_t*)&p0;
        pk.y = *(uint32_t*)&p1;
        *(uint2*)(dst + dbase + (size_t)np * K + k0 + kl) = pk;
    }
}

// ---------------- K1: fused prep = zero | route | cvt_x | W1T | W2T ----------
#define PREP_BLOCKS (2048 + 1 + 2048 + 8192 + 4096)

__global__ void __launch_bounds__(256) prep_kernel(const float4* __restrict__ x,
                                                   const int* __restrict__ idx,
                                                   float4* __restrict__ out,
                                                   const float* __restrict__ W1,
                                                   const float* __restrict__ W2) {
    __shared__ __align__(16) char tsm[64 * 33 * 4];
    __shared__ int cnt8[E_];
    const int bx = blockIdx.x, tid = threadIdx.x;

    if (bx < 2048) {                                     // zero output
        out[bx * 256 + tid] = make_float4(0.f, 0.f, 0.f, 0.f);
    } else if (bx == 2048) {                             // route (single block)
        if (tid < E_) cnt8[tid] = 0;
        __syncthreads();
        for (int j = 0; j < 16; j++) {
            int i = tid + 256 * j;                       // 4096 pairs
            int e = idx[i];
            int pos = atomicAdd(&cnt8[e], 1);
            g_perm[e * NPAIR_ + pos] = i;
        }
        __syncthreads();
        if (tid < E_) g_cnt[tid] = cnt8[tid];
    } else if (bx < 4097) {                              // cvt x -> fp16
        int i = (bx - 2049) * 256 + tid;                 // 512K float4
        float4 v = x[i];
        ((__half2*)g_xh)[2 * i]     = __floats2half2_rn(v.x, v.y);
        ((__half2*)g_xh)[2 * i + 1] = __floats2half2_rn(v.z, v.w);
    } else if (bx < 12289) {                             // W1 transpose+interleave
        int b   = bx - 4097;
        int e   = b >> 10;
        int rem = b & 1023;
        transpose_tile(W1, g_w1h, H2_, e, rem & 15, rem >> 4, true, tsm);
    } else {                                             // W2 transpose
        int b   = bx - 12289;
        int e   = b >> 9;
        int rem = b & 511;
        transpose_tile(W2, g_w2h, H_, e, rem & 15, rem >> 4, false, tsm);
    }
}

// ---------------- warp-level helpers ------------------------------------------
__device__ __forceinline__ void mma16816(float* c, const uint32_t* a, const uint32_t* b) {
    asm volatile(
        "mma.sync.aligned.m16n8k16.row.col.f32.f16.f16.f32 "
        "{%0,%1,%2,%3}, {%4,%5,%6,%7}, {%8,%9}, {%0,%1,%2,%3};"
        : "+f"(c[0]), "+f"(c[1]), "+f"(c[2]), "+f"(c[3])
        : "r"(a[0]), "r"(a[1]), "r"(a[2]), "r"(a[3]), "r"(b[0]), "r"(b[1]));
}
__device__ __forceinline__ void ldsm4(uint32_t* d, uint32_t a) {
    asm volatile("ldmatrix.sync.aligned.m8n8.x4.shared.b16 {%0,%1,%2,%3}, [%4];"
                 : "=r"(d[0]), "=r"(d[1]), "=r"(d[2]), "=r"(d[3]) : "r"(a));
}
__device__ __forceinline__ void cpasync16(uint32_t dst, const void* src, int sz) {
    asm volatile("cp.async.cg.shared.global [%0], [%1], 16, %2;"
                 :: "r"(dst), "l"(src), "r"(sz) : "memory");
}
__device__ __forceinline__ uint32_t smem_u32(const void* p) {
    uint32_t a;
    asm("{ .reg .u64 t; cvta.to.shared.u64 t, %1; cvt.u32.u64 %0, t; }" : "=r"(a) : "l"(p));
    return a;
}

// ---------------- GEMM: R9 engine (proven fastest) ---------------------------
// 128x128 CTA, 8 warps (2x4), warp 64x32, KC=64, 3-stage cp.async, 2 CTAs/SM,
// fragment double buffering, fp32-acc HMMA.
#define KC       64
#define STAGE_B  32768
#define NSTAGE   3
#define SMEM_DYN (1024 + NSTAGE * STAGE_B)
#define MTMAX    (NPAIR_ / 128)

__global__ void __launch_bounds__(256, 2) moe_gemm_kernel(
    const float* __restrict__ pgate, float* __restrict__ out, int mode, int Ntot)
{
    const int e     = blockIdx.z;
    const int cnt   = g_cnt[e];
    const int mTile = blockIdx.y;
    if (mTile * 128 >= cnt) return;
    const int nTile = blockIdx.x;

    extern __shared__ char smem[];
    int* rowoff = (int*)smem;
    const uint32_t sbase = smem_u32(smem);

    const int tid  = threadIdx.x;
    const int wid  = tid >> 5;
    const int lane = tid & 31;
    const int wm   = wid & 1;
    const int wn   = wid >> 1;

    const __half* A  = (mode == 1) ? g_xh  : g_ah;
    const __half* Bh = (mode == 1) ? g_w1h : g_w2h;
    Bh += ((size_t)e * Ntot + (size_t)nTile * 128) * 1024;

    if (tid < 128) {
        int rg = mTile * 128 + tid;
        int off = -1;
        if (rg < cnt) {
            int pair = g_perm[e * NPAIR_ + rg];
            off = (mode == 1) ? ((pair >> 1) << 10) : (pair << 10);
        }
        rowoff[tid] = off;
    }
    __syncthreads();

    const int lr  = tid >> 1;
    const int lcb = (tid & 1) * 4;
    const int lrx = lr & 7;
    auto issue_stage = [&](int c) {
        const int k0 = c * KC;
        const uint32_t stb = sbase + 1024 + (c % NSTAGE) * STAGE_B;
        const uint32_t dA = stb + lr * 128;
        int ao = rowoff[lr];
        int sz = (ao >= 0) ? 16 : 0;
        const __half* aph = A  + (ao >= 0 ? ao : 0) + k0 + lcb * 8;
        const __half* bph = Bh + (size_t)lr * 1024 + k0 + lcb * 8;
        #pragma unroll
        for (int i = 0; i < 4; i++) {
            uint32_t sw = (uint32_t)(((lcb + i) ^ lrx) << 4);
            cpasync16(dA + sw,         aph + i * 8, sz);
            cpasync16(dA + 16384 + sw, bph + i * 8, 16);
        }
        asm volatile("cp.async.commit_group;" ::: "memory");
    };

    const int g  = lane >> 3;
    const int r8 = lane & 7;
    uint32_t aRowOff[4], bRowOff[2];
    #pragma unroll
    for (int mf = 0; mf < 4; mf++)
        aRowOff[mf] = (uint32_t)((wm * 64 + mf * 16 + (g & 1) * 8 + r8) * 128);
    #pragma unroll
    for (int j = 0; j < 2; j++)
        bRowOff[j] = (uint32_t)((wn * 32 + j * 16 + (g >> 1) * 8 + r8) * 128) + 16384;
    const int acadd = g >> 1;
    const int bcadd = g & 1;

    float acc[4][4][4];
    #pragma unroll
    for (int i = 0; i < 4; i++)
        #pragma unroll
        for (int j = 0; j < 4; j++)
            #pragma unroll
            for (int q = 0; q < 4; q++) acc[i][j][q] = 0.f;

    uint32_t ah[2][4][4], bh[2][2][4];
    auto load_frags = [&](uint32_t stb, int s, int buf) {
        const uint32_t asw = (uint32_t)((((s * 2 + acadd) ^ r8) << 4));
        const uint32_t bsw = (uint32_t)((((s * 2 + bcadd) ^ r8) << 4));
        #pragma unroll
        for (int mf = 0; mf < 4; mf++)
            ldsm4(ah[buf][mf], stb + aRowOff[mf] + asw);
        #pragma unroll
        for (int j = 0; j < 2; j++)
            ldsm4(bh[buf][j], stb + bRowOff[j] + bsw);
    };

    issue_stage(0);
    issue_stage(1);

    const int NCH = 1024 / KC;   // 16
    for (int c = 0; c < NCH; c++) {
        if (c < NCH - 1) asm volatile("cp.async.wait_group 1;" ::: "memory");
        else             asm volatile("cp.async.wait_group 0;" ::: "memory");
        __syncthreads();
        if (c + 2 < NCH) issue_stage(c + 2);

        const uint32_t stb = sbase + 1024 + (c % NSTAGE) * STAGE_B;
        load_frags(stb, 0, 0);
        #pragma unroll
        for (int s = 0; s < 4; s++) {
            const int cur = s & 1;
            if (s < 3) load_frags(stb, s + 1, cur ^ 1);
            #pragma unroll
            for (int mf = 0; mf < 4; mf++)
                #pragma unroll
                for (int nf = 0; nf < 4; nf++) {
                    const int jj = nf >> 1, hh = nf & 1;
                    uint32_t bhp[2] = { bh[cur][jj][2 * hh], bh[cur][jj][2 * hh + 1] };
                    mma16816(acc[mf][nf], ah[cur][mf], bhp);
                }
        }
    }

    // ---- epilogue ----
    const int gr  = lane >> 2;
    const int lc2 = (lane & 3) * 2;
    #pragma unroll
    for (int mf = 0; mf < 4; mf++) {
        #pragma unroll
        for (int half = 0; half < 2; half++) {
            int r   = wm * 64 + mf * 16 + gr + half * 8;
            int rg2 = mTile * 128 + r;
            if (rg2 < cnt) {
                int pair = g_perm[e * NPAIR_ + rg2];
                if (mode == 1) {
                    __half* dst = g_ah + (size_t)pair * H_ + (size_t)nTile * 64;
                    #pragma unroll
                    for (int nf = 0; nf < 4; nf++) {
                        float h  = acc[mf][nf][half * 2];
                        float gg = acc[mf][nf][half * 2 + 1];
                        float a  = h * gg / (1.f + __expf(-gg));
                        int n = (wn * 32 + nf * 8 + lc2) >> 1;
                        dst[n] = __float2half_rn(a);
                    }
                } else {
                    float pc = pgate[pair];
                    float* dst = out + (size_t)(pair >> 1) * D_ + (size_t)nTile * 128;
                    #pragma unroll
                    for (int nf = 0; nf < 4; nf++) {
                        int n = wn * 32 + nf * 8 + lc2;
                        atomicAdd(dst + n,     acc[mf][nf][half * 2]     * pc);
                        atomicAdd(dst + n + 1, acc[mf][nf][half * 2 + 1] * pc);
                    }
                }
            }
        }
    }
}

// ---------------- launch ------------------------------------------------------
extern "C" void kernel_launch(void* const* d_in, const int* in_sizes, int n_in,
                              void* d_out, int out_size) {
    const float* x   = (const float*)d_in[0];   // [2,1024,1024] f32
    const float* p   = (const float*)d_in[1];   // [2048,2]      f32
    const int*   idx = (const int*)  d_in[2];   // [2048,2]      int32
    const float* W1  = (const float*)d_in[3];   // [8,1024,2048] f32
    const float* W2  = (const float*)d_in[4];   // [8,1024,1024] f32
    float*       out = (float*)d_out;           // [2,1024,1024] f32
    (void)in_sizes; (void)n_in; (void)out_size;

    cudaFuncSetAttribute(moe_gemm_kernel,
                         cudaFuncAttributeMaxDynamicSharedMemorySize, SMEM_DYN);

    // K1: zero + route + cvt_x + W1T + W2T (fused; 29.7us measured in R11)
    prep_kernel<<<PREP_BLOCKS, 256>>>((const float4*)x, idx, (float4*)out, W1, W2);
    // K2: GEMM1 (+fused SiLU epilogue)   — R9 engine, fp32-acc
    moe_gemm_kernel<<<dim3(H2_/128, MTMAX, E_), 256, SMEM_DYN>>>(p, out, 1, H2_);
    // K3: GEMM2 (+gated atomic combine)  — R9 engine, fp32-acc
    moe_gemm_kernel<<<dim3(D_/128, MTMAX, E_), 256, SMEM_DYN>>>(p, out, 2, D_);
}